// round 2
// baseline (speedup 1.0000x reference)
#include <cuda_runtime.h>

// IDCT (DCT-III) of B=4096 rows, N=4096, via Makhoul + Hermitian-packed
// 2048-point complex inverse FFT per row (radix-4 Stockham in shared memory).
//
//   V_k = (x_k - j x_{N-k}) * e^{j pi k/(2N)}   (x_N := 0)   -- e^{j..} == expk input
//   Z_k = (V_k + conj(V_{M-k})) + j e^{j 2pi k/N} (V_k - conj(V_{M-k})),  M = N/2
//   z   = unnormalized IDFT_M(Z)
//   y[4s+0] = Re z_s ; y[4s+1] = Im z_{M-1-s} ; y[4s+2] = Im z_s ; y[4s+3] = Re z_{M-1-s}

#define NN 4096
#define MM 2048
#define THREADS 256

// Twiddle table: g_W[k] = e^{+j 2 pi k / 4096}, k = 0..2047
__device__ float2 g_W[MM];

__global__ void setup_twiddles() {
    int k = blockIdx.x * blockDim.x + threadIdx.x;
    if (k < MM) {
        float s, c;
        sincospif((float)k / 2048.0f, &s, &c);   // angle = pi*k/2048 = 2*pi*k/4096
        g_W[k] = make_float2(c, s);
    }
}

__device__ __forceinline__ float2 cadd(float2 a, float2 b) { return make_float2(a.x + b.x, a.y + b.y); }
__device__ __forceinline__ float2 csub(float2 a, float2 b) { return make_float2(a.x - b.x, a.y - b.y); }
__device__ __forceinline__ float2 cmul(float2 a, float2 b) {
    return make_float2(fmaf(a.x, b.x, -a.y * b.y), fmaf(a.x, b.y, a.y * b.x));
}
__device__ __forceinline__ float2 csqr(float2 a) {
    return make_float2(fmaf(a.x, a.x, -a.y * a.y), 2.0f * a.x * a.y);
}

// One radix-4 Stockham pass (inverse FFT sign, +j). Total n = 2048.
// Each thread does 2 butterflies: b = tid, tid+256 (512 butterflies total).
template <int S, int LOG2S>
__device__ __forceinline__ void r4_stage(const float2* __restrict__ in,
                                         float2* __restrict__ out,
                                         const float2* __restrict__ tw, int tid) {
#pragma unroll
    for (int u = 0; u < 2; u++) {
        int b = tid + u * THREADS;
        int p = b >> LOG2S;                 // q = b & (S-1);  b = p*S + q
        float2 a  = in[b];
        float2 bb = in[b + 512];
        float2 c  = in[b + 1024];
        float2 d  = in[b + 1536];
        float2 apc = cadd(a, c), amc = csub(a, c);
        float2 bpd = cadd(bb, d);
        float2 jbmd = make_float2(-(bb.y - d.y), bb.x - d.x);   // j*(b-d)
        float2 w1 = tw[2 * S * p];          // e^{+j 2 pi p S / 2048} = g_W[2*S*p]
        float2 w2 = csqr(w1);
        float2 w3 = cmul(w1, w2);
        float2 y0 = cadd(apc, bpd);
        float2 y1 = cmul(w1, cadd(amc, jbmd));
        float2 y2 = cmul(w2, csub(apc, bpd));
        float2 y3 = cmul(w3, csub(amc, jbmd));
        int base = b + 3 * S * p;           // = q + 4*S*p
        if (S == 1) {
            // 4 contiguous complex outputs -> two float4 stores.
            // base = 4p (even); float4 index = base/2.
            float4* o = (float4*)out;
            o[(base >> 1)]     = make_float4(y0.x, y0.y, y1.x, y1.y);
            o[(base >> 1) + 1] = make_float4(y2.x, y2.y, y3.x, y3.y);
        } else {
            out[base]         = y0;
            out[base + S]     = y1;
            out[base + 2 * S] = y2;
            out[base + 3 * S] = y3;
        }
    }
}

__global__ __launch_bounds__(THREADS) void idct_kernel(const float* __restrict__ x,
                                                       const float2* __restrict__ expk,
                                                       float* __restrict__ y) {
    extern __shared__ float smem[];
    float*  sx   = smem;                       // 4097 floats (x row + trailing 0)
    float2* bufB = (float2*)smem;              // aliases sx (sx dead after Z build)
    float2* bufA = (float2*)(smem + 4100);     // 2048 complex, 16B aligned (4100*4=16400)
    float2* tw   = bufA + MM;                  // 1024 complex twiddles

    const int tid = threadIdx.x;
    const float* xr = x + (size_t)blockIdx.x * NN;

    // Stage twiddles (first 1024 entries) to SMEM
#pragma unroll
    for (int i = 0; i < 4; i++) {
        int k = tid + i * THREADS;
        tw[k] = g_W[k];
    }
    // Load x row (vectorized)
#pragma unroll
    for (int i = 0; i < 4; i++) {
        int idx = tid + i * THREADS;
        ((float4*)sx)[idx] = ((const float4*)xr)[idx];
    }
    if (tid == 0) sx[NN] = 0.0f;
    __syncthreads();

    // Build Z into bufA
#pragma unroll
    for (int i = 0; i < 8; i++) {
        int k = tid + i * THREADS;
        float xk   = sx[k];
        float xnk  = sx[NN - k];
        float xmk  = sx[MM - k];
        float xmpk = sx[MM + k];
        float2 E1 = expk[k];        // (cos t, -sin t), t = pi*k/(2N)
        float2 E2 = expk[MM - k];
        float c1 = E1.x, s1 = -E1.y;
        float c2 = E2.x, s2 = -E2.y;
        // V_k    = (xk  - j xnk ) * (c1 + j s1)
        float2 Vk = make_float2(fmaf(xk, c1, xnk * s1), fmaf(xk, s1, -xnk * c1));
        // V_{M-k}= (xmk - j xmpk) * (c2 + j s2)
        float2 Vm = make_float2(fmaf(xmk, c2, xmpk * s2), fmaf(xmk, s2, -xmpk * c2));
        float2 P = make_float2(Vk.x + Vm.x, Vk.y - Vm.y);   // V_k + conj(V_{M-k})
        float2 Q = make_float2(Vk.x - Vm.x, Vk.y + Vm.y);   // V_k - conj(V_{M-k})
        float2 W = g_W[k];                                  // e^{+j 2 pi k/4096}
        // Z = P + (jW)*Q,  jW = (-W.y, W.x)
        float zr = P.x - W.y * Q.x - W.x * Q.y;
        float zi = P.y + W.x * Q.x - W.y * Q.y;
        bufA[k] = make_float2(zr, zi);
    }
    __syncthreads();

    // 2048-point inverse FFT: 5 radix-4 Stockham passes + 1 radix-2
    r4_stage<1, 0>(bufA, bufB, tw, tid);   __syncthreads();
    r4_stage<4, 2>(bufB, bufA, tw, tid);   __syncthreads();
    r4_stage<16, 4>(bufA, bufB, tw, tid);  __syncthreads();
    r4_stage<64, 6>(bufB, bufA, tw, tid);  __syncthreads();
    r4_stage<256, 8>(bufA, bufB, tw, tid); __syncthreads();
    // radix-2, S = 1024, w = 1
#pragma unroll
    for (int u = 0; u < 4; u++) {
        int q = tid + u * THREADS;
        float2 a = bufB[q];
        float2 b = bufB[q + 1024];
        bufA[q]        = cadd(a, b);
        bufA[q + 1024] = csub(a, b);
    }
    __syncthreads();

    // Output permutation, coalesced float4 stores
    float4* yr = (float4*)(y + (size_t)blockIdx.x * NN);
#pragma unroll
    for (int u = 0; u < 4; u++) {
        int s0 = tid + u * THREADS;
        float2 zs = bufA[s0];
        float2 zt = bufA[2047 - s0];
        yr[s0] = make_float4(zs.x, zt.y, zs.y, zt.x);
    }
}

extern "C" void kernel_launch(void* const* d_in, const int* in_sizes, int n_in,
                              void* d_out, int out_size) {
    const float*  x    = (const float*)d_in[0];
    const float2* expk = (const float2*)d_in[1];
    float*        y    = (float*)d_out;

    int rows = in_sizes[0] / NN;   // 4096

    setup_twiddles<<<(MM + 255) / 256, 256>>>();

    size_t smem_bytes = 4100 * sizeof(float)      // sx (+pad)
                      + MM * sizeof(float2)       // bufA
                      + 1024 * sizeof(float2);    // tw
    idct_kernel<<<rows, THREADS, smem_bytes>>>(x, expk, y);
}

// round 3
// speedup vs baseline: 1.4776x; 1.4776x over previous
#include <cuda_runtime.h>

// IDCT (DCT-III), B=4096 rows, N=4096. Makhoul + Hermitian-packed 2048-pt
// complex inverse FFT per row. Radix 2048 = 8*8*8*4:
//   - Z build fused into first radix-8 (registers)
//   - two SMEM-exchanged radix-8 stages
//   - final radix-4 fused with output permutation (thread-local pairing)
// All twiddles derived from expk: (e^{j*pi*m/8192})^4 = W_2048^m.

#define NN 4096
#define MM 2048
#define THREADS 256
#define PAD(m) ((m) + ((m) >> 3))   // float2 buffers padded 1 per 8

__device__ __forceinline__ float2 cadd(float2 a, float2 b) { return make_float2(a.x + b.x, a.y + b.y); }
__device__ __forceinline__ float2 csub(float2 a, float2 b) { return make_float2(a.x - b.x, a.y - b.y); }
__device__ __forceinline__ float2 cmul(float2 a, float2 b) {
    return make_float2(fmaf(a.x, b.x, -a.y * b.y), fmaf(a.x, b.y, a.y * b.x));
}
__device__ __forceinline__ float2 csqr(float2 a) {
    return make_float2(fmaf(a.x, a.x, -a.y * a.y), 2.0f * a.x * a.y);
}

// W_2048^idx = (e^{+j*pi*idx/8192})^4 ; expk[idx] = (cos t, -sin t), t = pi*idx/8192
__device__ __forceinline__ float2 tw_from_expk(const float2* __restrict__ expk, int idx) {
    float2 E = __ldg(&expk[idx]);
    float2 e = make_float2(E.x, -E.y);   // e^{+j t}
    e = csqr(e);
    e = csqr(e);
    return e;
}

// Inverse DFT-8 (+j convention), radix-2(radix-4) split.
__device__ __forceinline__ void idft8(const float2 a[8], float2 X[8]) {
    const float C = 0.70710678118654752f;
    float2 p0 = cadd(a[0], a[4]), m0 = csub(a[0], a[4]);
    float2 q0 = cadd(a[2], a[6]);
    float2 r0 = make_float2(-(a[2].y - a[6].y), a[2].x - a[6].x);   // j(a2-a6)
    float2 E0 = cadd(p0, q0), E1 = cadd(m0, r0), E2 = csub(p0, q0), E3 = csub(m0, r0);
    float2 p1 = cadd(a[1], a[5]), m1 = csub(a[1], a[5]);
    float2 q1 = cadd(a[3], a[7]);
    float2 r1 = make_float2(-(a[3].y - a[7].y), a[3].x - a[7].x);
    float2 O0 = cadd(p1, q1), O1 = cadd(m1, r1), O2 = csub(p1, q1), O3 = csub(m1, r1);
    float2 T1 = make_float2(C * (O1.x - O1.y), C * (O1.x + O1.y));       // w8^1 * O1
    float2 T2 = make_float2(-O2.y, O2.x);                                // j * O2
    float2 T3 = make_float2(-C * (O3.x + O3.y), C * (O3.x - O3.y));      // w8^3 * O3
    X[0] = cadd(E0, O0); X[4] = csub(E0, O0);
    X[1] = cadd(E1, T1); X[5] = csub(E1, T1);
    X[2] = cadd(E2, T2); X[6] = csub(E2, T2);
    X[3] = cadd(E3, T3); X[7] = csub(E3, T3);
}

// Twiddle (w1 = W_2048^{S*p}) application + padded store: out[m_i], m_i = base + i*S.
__device__ __forceinline__ void tw_store(float2* __restrict__ out, const float2 X[8],
                                         float2 w1, int base, int S) {
    out[PAD(base)]         = X[0];
    out[PAD(base + S)]     = cmul(w1, X[1]);
    float2 w2 = csqr(w1);
    out[PAD(base + 2 * S)] = cmul(w2, X[2]);
    float2 w3 = cmul(w1, w2);
    out[PAD(base + 3 * S)] = cmul(w3, X[3]);
    float2 w4 = csqr(w2);
    out[PAD(base + 4 * S)] = cmul(w4, X[4]);
    float2 w5 = cmul(w2, w3);
    out[PAD(base + 5 * S)] = cmul(w5, X[5]);
    float2 w6 = csqr(w3);
    out[PAD(base + 6 * S)] = cmul(w6, X[6]);
    float2 w7 = cmul(w3, w4);
    out[PAD(base + 7 * S)] = cmul(w7, X[7]);
}

__global__ __launch_bounds__(THREADS, 5)
void idct_kernel(const float* __restrict__ x,
                 const float2* __restrict__ expk,
                 float* __restrict__ y) {
    extern __shared__ float smem[];
    // bufB (2304 float2, 18432B) at offset 0; x staged in same region (4097 floats).
    float*  sx   = smem;
    float2* bufB = (float2*)smem;
    float2* bufA = (float2*)(smem + 4608);   // 18432B offset, 16B aligned

    const int tid = threadIdx.x;
    const float* xr = x + (size_t)blockIdx.x * NN;

    // Stage x row into SMEM (vectorized)
#pragma unroll
    for (int i = 0; i < 4; i++) {
        int idx = tid + i * THREADS;
        ((float4*)sx)[idx] = ((const float4*)xr)[idx];
    }
    if (tid == 0) sx[NN] = 0.0f;
    __syncthreads();

    // ---- Z build (registers) + radix-8 stage 1 (S=1, p=tid) -> bufA ----
    {
        float2 Z[8];
#pragma unroll
        for (int i = 0; i < 8; i++) {
            int k = tid + i * THREADS;
            float xk   = sx[k];
            float xnk  = sx[NN - k];
            float xmk  = sx[MM - k];
            float xmpk = sx[MM + k];
            float2 E1 = __ldg(&expk[k]);        // (cos t, -sin t), t = pi*k/8192
            float2 E2 = __ldg(&expk[MM - k]);
            float c1 = E1.x, s1 = -E1.y;
            float c2 = E2.x, s2 = -E2.y;
            float2 Vk = make_float2(fmaf(xk, c1, xnk * s1), fmaf(xk, s1, -xnk * c1));
            float2 Vm = make_float2(fmaf(xmk, c2, xmpk * s2), fmaf(xmk, s2, -xmpk * c2));
            float2 P = make_float2(Vk.x + Vm.x, Vk.y - Vm.y);   // V_k + conj(V_{M-k})
            float2 Q = make_float2(Vk.x - Vm.x, Vk.y + Vm.y);   // V_k - conj(V_{M-k})
            float2 W = csqr(csqr(make_float2(c1, s1)));          // e^{j*2pi*k/4096}
            Z[i] = make_float2(P.x - W.y * Q.x - W.x * Q.y,
                               P.y + W.x * Q.x - W.y * Q.y);
        }
        float2 X[8];
        idft8(Z, X);
        float2 w1 = tw_from_expk(expk, 2 * tid);   // W_2048^{tid}
        tw_store(bufA, X, w1, 8 * tid, 1);
    }
    __syncthreads();

    // ---- radix-8 stage 2 (S=8): bufA -> bufB ----
    {
        int p = tid >> 3, q = tid & 7;
        float2 a[8], X[8];
#pragma unroll
        for (int i = 0; i < 8; i++) a[i] = bufA[PAD(tid + 256 * i)];
        idft8(a, X);
        float2 w1 = tw_from_expk(expk, 16 * p);    // W_2048^{8p}
        tw_store(bufB, X, w1, q + 64 * p, 8);
    }
    __syncthreads();

    // ---- radix-8 stage 3 (S=64): bufB -> bufA ----
    {
        int p = tid >> 6, q = tid & 63;
        float2 a[8], X[8];
#pragma unroll
        for (int i = 0; i < 8; i++) a[i] = bufB[PAD(tid + 256 * i)];
        idft8(a, X);
        float2 w1 = tw_from_expk(expk, 128 * p);   // W_2048^{64p}
        tw_store(bufA, X, w1, q + 512 * p, 64);
    }
    __syncthreads();

    // ---- radix-4 stage 4 (S=512, trivial twiddle) fused with output perm ----
    // Thread handles butterflies b1=tid and b2=511-tid so every (z_s, z_{2047-s})
    // pair is thread-local:  2047-(b+512i) = (511-b) + 512*(3-i).
    {
        const int b1 = tid, b2 = 511 - tid;
        float2 a0 = bufA[PAD(b1)],        a1 = bufA[PAD(b1 + 512)];
        float2 a2 = bufA[PAD(b1 + 1024)], a3 = bufA[PAD(b1 + 1536)];
        float2 c0 = bufA[PAD(b2)],        c1 = bufA[PAD(b2 + 512)];
        float2 c2 = bufA[PAD(b2 + 1024)], c3 = bufA[PAD(b2 + 1536)];

        float2 apc = cadd(a0, a2), amc = csub(a0, a2);
        float2 bpd = cadd(a1, a3);
        float2 jbmd = make_float2(-(a1.y - a3.y), a1.x - a3.x);
        float2 z0 = cadd(apc, bpd);    // z_{b1}
        float2 z1 = cadd(amc, jbmd);   // z_{b1+512}
        float2 z2 = csub(apc, bpd);    // z_{b1+1024}
        float2 z3 = csub(amc, jbmd);   // z_{b1+1536}

        float2 cpc = cadd(c0, c2), cmc = csub(c0, c2);
        float2 dpd = cadd(c1, c3);
        float2 jdmd = make_float2(-(c1.y - c3.y), c1.x - c3.x);
        float2 Z0 = cadd(cpc, dpd);    // z_{b2}
        float2 Z1 = cadd(cmc, jdmd);   // z_{b2+512}
        float2 Z2 = csub(cpc, dpd);    // z_{b2+1024}
        float2 Z3 = csub(cmc, jdmd);   // z_{b2+1536}

        // y[4s..4s+3] = {Re z_s, Im z_{2047-s}, Im z_s, Re z_{2047-s}}
        float4* yr = (float4*)(y + (size_t)blockIdx.x * NN);
        yr[b1]       = make_float4(z0.x, Z3.y, z0.y, Z3.x);   // s=b1,     partner z_{b2+1536}
        yr[b1 + 512] = make_float4(z1.x, Z2.y, z1.y, Z2.x);   // s=b1+512, partner z_{b2+1024}
        yr[b2]       = make_float4(Z0.x, z3.y, Z0.y, z3.x);   // s=b2,     partner z_{b1+1536}
        yr[b2 + 512] = make_float4(Z1.x, z2.y, Z1.y, z2.x);   // s=b2+512, partner z_{b1+1024}
    }
}

extern "C" void kernel_launch(void* const* d_in, const int* in_sizes, int n_in,
                              void* d_out, int out_size) {
    const float*  x    = (const float*)d_in[0];
    const float2* expk = (const float2*)d_in[1];
    float*        y    = (float*)d_out;

    int rows = in_sizes[0] / NN;   // 4096
    size_t smem_bytes = 2 * 2304 * sizeof(float2);   // 36864B: bufB | bufA (padded)
    idct_kernel<<<rows, THREADS, smem_bytes>>>(x, expk, y);
}

// round 4
// speedup vs baseline: 1.5663x; 1.0601x over previous
#include <cuda_runtime.h>

// IDCT (DCT-III), B=4096 rows, N=4096. Makhoul + Hermitian-packed 2048-pt
// complex inverse FFT per row. 2048 = 16 * 16 * 8, 128 threads, 16 pts/thread:
//   stage1 radix-16 fused with Z build (x read directly from global)
//   stage2 radix-16 (one SMEM exchange before, one after)
//   stage3 radix-8 (trivial twiddles) fused with output permutation
// SMEM: two 2048-float2 buffers, XOR-swizzled (no padding).

#define NN 4096
#define MM 2048
#define THREADS 128
#define SW(m) ((m) ^ (((m) >> 4) & 15))

__device__ __forceinline__ float2 cadd(float2 a, float2 b) { return make_float2(a.x + b.x, a.y + b.y); }
__device__ __forceinline__ float2 csub(float2 a, float2 b) { return make_float2(a.x - b.x, a.y - b.y); }
__device__ __forceinline__ float2 cmul(float2 a, float2 b) {
    return make_float2(fmaf(a.x, b.x, -a.y * b.y), fmaf(a.x, b.y, a.y * b.x));
}
__device__ __forceinline__ float2 csqr(float2 a) {
    return make_float2(fmaf(a.x, a.x, -a.y * a.y), 2.0f * a.x * a.y);
}

// W_2048^{idx/2} = (e^{+j*pi*idx/8192})^4 ; expk[idx] = (cos t, -sin t)
__device__ __forceinline__ float2 tw_from_expk(const float2* __restrict__ expk, int idx) {
    float2 E = __ldg(&expk[idx]);
    float2 e = make_float2(E.x, -E.y);
    e = csqr(e);
    e = csqr(e);
    return e;
}

// Inverse DFT-8 (+j convention).
__device__ __forceinline__ void idft8(const float2 a[8], float2 X[8]) {
    const float C = 0.70710678118654752f;
    float2 p0 = cadd(a[0], a[4]), m0 = csub(a[0], a[4]);
    float2 q0 = cadd(a[2], a[6]);
    float2 r0 = make_float2(-(a[2].y - a[6].y), a[2].x - a[6].x);
    float2 E0 = cadd(p0, q0), E1 = cadd(m0, r0), E2 = csub(p0, q0), E3 = csub(m0, r0);
    float2 p1 = cadd(a[1], a[5]), m1 = csub(a[1], a[5]);
    float2 q1 = cadd(a[3], a[7]);
    float2 r1 = make_float2(-(a[3].y - a[7].y), a[3].x - a[7].x);
    float2 O0 = cadd(p1, q1), O1 = cadd(m1, r1), O2 = csub(p1, q1), O3 = csub(m1, r1);
    float2 T1 = make_float2(C * (O1.x - O1.y), C * (O1.x + O1.y));
    float2 T2 = make_float2(-O2.y, O2.x);
    float2 T3 = make_float2(-C * (O3.x + O3.y), C * (O3.x - O3.y));
    X[0] = cadd(E0, O0); X[4] = csub(E0, O0);
    X[1] = cadd(E1, T1); X[5] = csub(E1, T1);
    X[2] = cadd(E2, T2); X[6] = csub(E2, T2);
    X[3] = cadd(E3, T3); X[7] = csub(E3, T3);
}

// Inverse DFT-16 (+j), 4x4 split:  n = n0 + 4*n1,  m = m0 + 4*m1.
__device__ __forceinline__ void idft16(const float2 a[16], float2 X[16]) {
    const float C8  = 0.70710678118654752f;
    const float C16 = 0.92387953251128674f;
    const float S16 = 0.38268343236508977f;
    float2 B[4][4];
#pragma unroll
    for (int n0 = 0; n0 < 4; n0++) {
        float2 A0 = a[n0], A1 = a[n0 + 4], A2 = a[n0 + 8], A3 = a[n0 + 12];
        float2 s02 = cadd(A0, A2), d02 = csub(A0, A2);
        float2 s13 = cadd(A1, A3);
        float2 jd13 = make_float2(-(A1.y - A3.y), A1.x - A3.x);
        B[n0][0] = cadd(s02, s13);
        B[n0][1] = cadd(d02, jd13);
        B[n0][2] = csub(s02, s13);
        B[n0][3] = csub(d02, jd13);
    }
    // m0 = 0: C_n0 = B[n0][0]
    {
        float2 C0 = B[0][0], C1 = B[1][0], C2 = B[2][0], C3 = B[3][0];
        float2 s = cadd(C0, C2), d = csub(C0, C2);
        float2 t = cadd(C1, C3);
        float2 jd13 = make_float2(-(C1.y - C3.y), C1.x - C3.x);
        X[0] = cadd(s, t); X[4] = cadd(d, jd13); X[8] = csub(s, t); X[12] = csub(d, jd13);
    }
    // m0 = 1: twiddles 1, W16, W16^2=(C8,C8), W16^3=(S16,C16)
    {
        float2 C0 = B[0][1];
        float2 C1 = cmul(make_float2(C16, S16), B[1][1]);
        float2 b2 = B[2][1];
        float2 C2 = make_float2(C8 * (b2.x - b2.y), C8 * (b2.x + b2.y));
        float2 C3 = cmul(make_float2(S16, C16), B[3][1]);
        float2 s = cadd(C0, C2), d = csub(C0, C2);
        float2 t = cadd(C1, C3);
        float2 jd13 = make_float2(-(C1.y - C3.y), C1.x - C3.x);
        X[1] = cadd(s, t); X[5] = cadd(d, jd13); X[9] = csub(s, t); X[13] = csub(d, jd13);
    }
    // m0 = 2: twiddles 1, (C8,C8), j, (-C8,C8)
    {
        float2 C0 = B[0][2];
        float2 b1 = B[1][2];
        float2 C1 = make_float2(C8 * (b1.x - b1.y), C8 * (b1.x + b1.y));
        float2 b2 = B[2][2];
        float2 C2 = make_float2(-b2.y, b2.x);
        float2 b3 = B[3][2];
        float2 C3 = make_float2(-C8 * (b3.x + b3.y), C8 * (b3.x - b3.y));
        float2 s = cadd(C0, C2), d = csub(C0, C2);
        float2 t = cadd(C1, C3);
        float2 jd13 = make_float2(-(C1.y - C3.y), C1.x - C3.x);
        X[2] = cadd(s, t); X[6] = cadd(d, jd13); X[10] = csub(s, t); X[14] = csub(d, jd13);
    }
    // m0 = 3: twiddles 1, (S16,C16), (-C8,C8), (-C16,-S16)
    {
        float2 C0 = B[0][3];
        float2 C1 = cmul(make_float2(S16, C16), B[1][3]);
        float2 b2 = B[2][3];
        float2 C2 = make_float2(-C8 * (b2.x + b2.y), C8 * (b2.x - b2.y));
        float2 b3 = B[3][3];
        float2 C3 = make_float2(-fmaf(C16, b3.x, -S16 * b3.y), -fmaf(C16, b3.y, S16 * b3.x));
        float2 s = cadd(C0, C2), d = csub(C0, C2);
        float2 t = cadd(C1, C3);
        float2 jd13 = make_float2(-(C1.y - C3.y), C1.x - C3.x);
        X[3] = cadd(s, t); X[7] = cadd(d, jd13); X[11] = csub(s, t); X[15] = csub(d, jd13);
    }
}

// Apply w1^i and store out[SW(base + i*S)] (squaring tree keeps chain short).
__device__ __forceinline__ void tw_store16(float2* __restrict__ out, const float2 X[16],
                                           float2 w1, int base, int S) {
    float2 w2 = csqr(w1);
    float2 w4 = csqr(w2);
    float2 w8 = csqr(w4);
    float2 w3 = cmul(w1, w2);
    float2 w5 = cmul(w1, w4);
    float2 w6 = cmul(w2, w4);
    float2 w7 = cmul(w3, w4);
    out[SW(base)]          = X[0];
    out[SW(base + S)]      = cmul(w1, X[1]);
    out[SW(base + 2 * S)]  = cmul(w2, X[2]);
    out[SW(base + 3 * S)]  = cmul(w3, X[3]);
    out[SW(base + 4 * S)]  = cmul(w4, X[4]);
    out[SW(base + 5 * S)]  = cmul(w5, X[5]);
    out[SW(base + 6 * S)]  = cmul(w6, X[6]);
    out[SW(base + 7 * S)]  = cmul(w7, X[7]);
    out[SW(base + 8 * S)]  = cmul(w8, X[8]);
    out[SW(base + 9 * S)]  = cmul(cmul(w1, w8), X[9]);
    out[SW(base + 10 * S)] = cmul(cmul(w2, w8), X[10]);
    out[SW(base + 11 * S)] = cmul(cmul(w3, w8), X[11]);
    out[SW(base + 12 * S)] = cmul(cmul(w4, w8), X[12]);
    out[SW(base + 13 * S)] = cmul(cmul(w5, w8), X[13]);
    out[SW(base + 14 * S)] = cmul(cmul(w6, w8), X[14]);
    out[SW(base + 15 * S)] = cmul(cmul(w7, w8), X[15]);
}

__global__ __launch_bounds__(THREADS)
void idct_kernel(const float* __restrict__ x,
                 const float2* __restrict__ expk,
                 float* __restrict__ y) {
    extern __shared__ float2 smem2[];
    float2* bufA = smem2;
    float2* bufB = smem2 + MM;

    const int tid = threadIdx.x;
    const float* xr = x + (size_t)blockIdx.x * NN;
    const float C8 = 0.70710678118654752f;

    // ---- Z build (direct global reads) + radix-16 stage 1 (S=1, p=tid) ----
    {
        float2 Z[16];
#pragma unroll
        for (int i = 0; i < 16; i++) {
            int k = tid + i * THREADS;
            float xk   = xr[k];
            float xnk  = (k == 0) ? 0.0f : xr[NN - k];
            float xmk  = xr[MM - k];
            float xmpk = xr[MM + k];
            float2 E1 = __ldg(&expk[k]);         // (cos t, -sin t), t = pi*k/8192
            float c1 = E1.x, s1 = -E1.y;
            // e^{j*pi*(2048-k)/8192} = e^{j*pi/4} * conj(e^{j*pi*k/8192})
            float c2 = C8 * (c1 + s1), s2 = C8 * (c1 - s1);
            float2 Vk = make_float2(fmaf(xk, c1, xnk * s1), fmaf(xk, s1, -xnk * c1));
            float2 Vm = make_float2(fmaf(xmk, c2, xmpk * s2), fmaf(xmk, s2, -xmpk * c2));
            float2 P = make_float2(Vk.x + Vm.x, Vk.y - Vm.y);   // V_k + conj(V_{M-k})
            float2 Q = make_float2(Vk.x - Vm.x, Vk.y + Vm.y);   // V_k - conj(V_{M-k})
            float2 W = csqr(csqr(make_float2(c1, s1)));          // e^{j*2pi*k/4096}
            Z[i] = make_float2(P.x - W.y * Q.x - W.x * Q.y,
                               P.y + W.x * Q.x - W.y * Q.y);
        }
        float2 X[16];
        idft16(Z, X);
        float2 w1 = tw_from_expk(expk, 2 * tid);   // W_2048^{tid}
        tw_store16(bufA, X, w1, 16 * tid, 1);
    }
    __syncthreads();

    // ---- radix-16 stage 2 (S=16): bufA -> bufB ----
    {
        float2 a[16], X[16];
#pragma unroll
        for (int i = 0; i < 16; i++) a[i] = bufA[SW(tid + 128 * i)];
        idft16(a, X);
        int p = tid >> 4, q = tid & 15;
        float2 w1 = tw_from_expk(expk, 32 * p);    // W_2048^{16p}
        tw_store16(bufB, X, w1, q + 256 * p, 16);
    }
    __syncthreads();

    // ---- radix-8 stage 3 (S=256, trivial twiddle) fused with output perm ----
    // Thread handles butterflies b1=tid, b2=255-tid: partner of z_{q+256i}
    // is z_{2047-(q+256i)} = z_{(255-q)+256(7-i)} -> thread-local.
    {
        const int b1 = tid, b2 = 255 - tid;
        float2 a1[8], a2[8], z1[8], z2[8];
#pragma unroll
        for (int i = 0; i < 8; i++) a1[i] = bufB[SW(b1 + 256 * i)];
#pragma unroll
        for (int i = 0; i < 8; i++) a2[i] = bufB[SW(b2 + 256 * i)];
        idft8(a1, z1);
        idft8(a2, z2);
        // y[4s..4s+3] = {Re z_s, Im z_{2047-s}, Im z_s, Re z_{2047-s}}
        float4* yr = (float4*)(y + (size_t)blockIdx.x * NN);
#pragma unroll
        for (int i = 0; i < 4; i++) {
            yr[b1 + 256 * i] = make_float4(z1[i].x, z2[7 - i].y, z1[i].y, z2[7 - i].x);
            yr[b2 + 256 * i] = make_float4(z2[i].x, z1[7 - i].y, z2[i].y, z1[7 - i].x);
        }
    }
}

extern "C" void kernel_launch(void* const* d_in, const int* in_sizes, int n_in,
                              void* d_out, int out_size) {
    const float*  x    = (const float*)d_in[0];
    const float2* expk = (const float2*)d_in[1];
    float*        y    = (float*)d_out;

    int rows = in_sizes[0] / NN;                     // 4096
    size_t smem_bytes = 2 * MM * sizeof(float2);     // 32 KB
    idct_kernel<<<rows, THREADS, smem_bytes>>>(x, expk, y);
}

// round 5
// speedup vs baseline: 1.8188x; 1.1612x over previous
#include <cuda_runtime.h>

// IDCT (DCT-III), B=4096 rows, N=4096. Makhoul + Hermitian-packed 2048-pt
// complex inverse FFT per row. 2048 = 16 * 16 * 8, 128 threads, 16 pts/thread:
//   stage1 radix-16 fused with Z build (x read directly from global)
//   stage2 radix-16, IN-PLACE (read all to regs, sync, write back)
//   stage3 radix-8 (trivial twiddles) fused with output permutation
// SMEM: ONE 2048-float2 buffer (16 KB), XOR-swizzled -> 9 CTAs/SM (56% occ).

#define NN 4096
#define MM 2048
#define THREADS 128
#define SW(m) ((m) ^ (((m) >> 4) & 15))

__device__ __forceinline__ float2 cadd(float2 a, float2 b) { return make_float2(a.x + b.x, a.y + b.y); }
__device__ __forceinline__ float2 csub(float2 a, float2 b) { return make_float2(a.x - b.x, a.y - b.y); }
__device__ __forceinline__ float2 cmul(float2 a, float2 b) {
    return make_float2(fmaf(a.x, b.x, -a.y * b.y), fmaf(a.x, b.y, a.y * b.x));
}
__device__ __forceinline__ float2 csqr(float2 a) {
    return make_float2(fmaf(a.x, a.x, -a.y * a.y), 2.0f * a.x * a.y);
}

// W_2048^{idx/2} = (e^{+j*pi*idx/8192})^4 ; expk[idx] = (cos t, -sin t)
__device__ __forceinline__ float2 tw_from_expk(const float2* __restrict__ expk, int idx) {
    float2 E = __ldg(&expk[idx]);
    float2 e = make_float2(E.x, -E.y);
    e = csqr(e);
    e = csqr(e);
    return e;
}

// Inverse DFT-8 (+j convention).
__device__ __forceinline__ void idft8(const float2 a[8], float2 X[8]) {
    const float C = 0.70710678118654752f;
    float2 p0 = cadd(a[0], a[4]), m0 = csub(a[0], a[4]);
    float2 q0 = cadd(a[2], a[6]);
    float2 r0 = make_float2(-(a[2].y - a[6].y), a[2].x - a[6].x);
    float2 E0 = cadd(p0, q0), E1 = cadd(m0, r0), E2 = csub(p0, q0), E3 = csub(m0, r0);
    float2 p1 = cadd(a[1], a[5]), m1 = csub(a[1], a[5]);
    float2 q1 = cadd(a[3], a[7]);
    float2 r1 = make_float2(-(a[3].y - a[7].y), a[3].x - a[7].x);
    float2 O0 = cadd(p1, q1), O1 = cadd(m1, r1), O2 = csub(p1, q1), O3 = csub(m1, r1);
    float2 T1 = make_float2(C * (O1.x - O1.y), C * (O1.x + O1.y));
    float2 T2 = make_float2(-O2.y, O2.x);
    float2 T3 = make_float2(-C * (O3.x + O3.y), C * (O3.x - O3.y));
    X[0] = cadd(E0, O0); X[4] = csub(E0, O0);
    X[1] = cadd(E1, T1); X[5] = csub(E1, T1);
    X[2] = cadd(E2, T2); X[6] = csub(E2, T2);
    X[3] = cadd(E3, T3); X[7] = csub(E3, T3);
}

// Inverse DFT-16 (+j), 4x4 split:  n = n0 + 4*n1,  m = m0 + 4*m1.
__device__ __forceinline__ void idft16(const float2 a[16], float2 X[16]) {
    const float C8  = 0.70710678118654752f;
    const float C16 = 0.92387953251128674f;
    const float S16 = 0.38268343236508977f;
    float2 B[4][4];
#pragma unroll
    for (int n0 = 0; n0 < 4; n0++) {
        float2 A0 = a[n0], A1 = a[n0 + 4], A2 = a[n0 + 8], A3 = a[n0 + 12];
        float2 s02 = cadd(A0, A2), d02 = csub(A0, A2);
        float2 s13 = cadd(A1, A3);
        float2 jd13 = make_float2(-(A1.y - A3.y), A1.x - A3.x);
        B[n0][0] = cadd(s02, s13);
        B[n0][1] = cadd(d02, jd13);
        B[n0][2] = csub(s02, s13);
        B[n0][3] = csub(d02, jd13);
    }
    // m0 = 0
    {
        float2 C0 = B[0][0], C1 = B[1][0], C2 = B[2][0], C3 = B[3][0];
        float2 s = cadd(C0, C2), d = csub(C0, C2);
        float2 t = cadd(C1, C3);
        float2 jd13 = make_float2(-(C1.y - C3.y), C1.x - C3.x);
        X[0] = cadd(s, t); X[4] = cadd(d, jd13); X[8] = csub(s, t); X[12] = csub(d, jd13);
    }
    // m0 = 1: twiddles 1, W16, W16^2=(C8,C8), W16^3=(S16,C16)
    {
        float2 C0 = B[0][1];
        float2 C1 = cmul(make_float2(C16, S16), B[1][1]);
        float2 b2 = B[2][1];
        float2 C2 = make_float2(C8 * (b2.x - b2.y), C8 * (b2.x + b2.y));
        float2 C3 = cmul(make_float2(S16, C16), B[3][1]);
        float2 s = cadd(C0, C2), d = csub(C0, C2);
        float2 t = cadd(C1, C3);
        float2 jd13 = make_float2(-(C1.y - C3.y), C1.x - C3.x);
        X[1] = cadd(s, t); X[5] = cadd(d, jd13); X[9] = csub(s, t); X[13] = csub(d, jd13);
    }
    // m0 = 2: twiddles 1, (C8,C8), j, (-C8,C8)
    {
        float2 C0 = B[0][2];
        float2 b1 = B[1][2];
        float2 C1 = make_float2(C8 * (b1.x - b1.y), C8 * (b1.x + b1.y));
        float2 b2 = B[2][2];
        float2 C2 = make_float2(-b2.y, b2.x);
        float2 b3 = B[3][2];
        float2 C3 = make_float2(-C8 * (b3.x + b3.y), C8 * (b3.x - b3.y));
        float2 s = cadd(C0, C2), d = csub(C0, C2);
        float2 t = cadd(C1, C3);
        float2 jd13 = make_float2(-(C1.y - C3.y), C1.x - C3.x);
        X[2] = cadd(s, t); X[6] = cadd(d, jd13); X[10] = csub(s, t); X[14] = csub(d, jd13);
    }
    // m0 = 3: twiddles 1, (S16,C16), (-C8,C8), (-C16,-S16)
    {
        float2 C0 = B[0][3];
        float2 C1 = cmul(make_float2(S16, C16), B[1][3]);
        float2 b2 = B[2][3];
        float2 C2 = make_float2(-C8 * (b2.x + b2.y), C8 * (b2.x - b2.y));
        float2 b3 = B[3][3];
        float2 C3 = make_float2(-fmaf(C16, b3.x, -S16 * b3.y), -fmaf(C16, b3.y, S16 * b3.x));
        float2 s = cadd(C0, C2), d = csub(C0, C2);
        float2 t = cadd(C1, C3);
        float2 jd13 = make_float2(-(C1.y - C3.y), C1.x - C3.x);
        X[3] = cadd(s, t); X[7] = cadd(d, jd13); X[11] = csub(s, t); X[15] = csub(d, jd13);
    }
}

// Apply w1^i and store out[SW(base + i*S)] (squaring tree keeps chain short).
__device__ __forceinline__ void tw_store16(float2* __restrict__ out, const float2 X[16],
                                           float2 w1, int base, int S) {
    float2 w2 = csqr(w1);
    float2 w4 = csqr(w2);
    float2 w8 = csqr(w4);
    float2 w3 = cmul(w1, w2);
    float2 w5 = cmul(w1, w4);
    float2 w6 = cmul(w2, w4);
    float2 w7 = cmul(w3, w4);
    out[SW(base)]          = X[0];
    out[SW(base + S)]      = cmul(w1, X[1]);
    out[SW(base + 2 * S)]  = cmul(w2, X[2]);
    out[SW(base + 3 * S)]  = cmul(w3, X[3]);
    out[SW(base + 4 * S)]  = cmul(w4, X[4]);
    out[SW(base + 5 * S)]  = cmul(w5, X[5]);
    out[SW(base + 6 * S)]  = cmul(w6, X[6]);
    out[SW(base + 7 * S)]  = cmul(w7, X[7]);
    out[SW(base + 8 * S)]  = cmul(w8, X[8]);
    out[SW(base + 9 * S)]  = cmul(cmul(w1, w8), X[9]);
    out[SW(base + 10 * S)] = cmul(cmul(w2, w8), X[10]);
    out[SW(base + 11 * S)] = cmul(cmul(w3, w8), X[11]);
    out[SW(base + 12 * S)] = cmul(cmul(w4, w8), X[12]);
    out[SW(base + 13 * S)] = cmul(cmul(w5, w8), X[13]);
    out[SW(base + 14 * S)] = cmul(cmul(w6, w8), X[14]);
    out[SW(base + 15 * S)] = cmul(cmul(w7, w8), X[15]);
}

__global__ __launch_bounds__(THREADS, 9)
void idct_kernel(const float* __restrict__ x,
                 const float2* __restrict__ expk,
                 float* __restrict__ y) {
    extern __shared__ float2 buf[];   // 2048 float2, in-place ping-pong via syncs

    const int tid = threadIdx.x;
    const float* xr = x + (size_t)blockIdx.x * NN;
    const float C8 = 0.70710678118654752f;

    // ---- Z build (direct global reads) + radix-16 stage 1 (S=1, p=tid) ----
    {
        float2 Z[16];
#pragma unroll
        for (int i = 0; i < 16; i++) {
            int k = tid + i * THREADS;
            float xk   = xr[k];
            float xnk  = (k == 0) ? 0.0f : xr[NN - k];
            float xmk  = xr[MM - k];
            float xmpk = xr[MM + k];
            float2 E1 = __ldg(&expk[k]);         // (cos t, -sin t), t = pi*k/8192
            float c1 = E1.x, s1 = -E1.y;
            // e^{j*pi*(2048-k)/8192} = e^{j*pi/4} * conj(e^{j*pi*k/8192})
            float c2 = C8 * (c1 + s1), s2 = C8 * (c1 - s1);
            float2 Vk = make_float2(fmaf(xk, c1, xnk * s1), fmaf(xk, s1, -xnk * c1));
            float2 Vm = make_float2(fmaf(xmk, c2, xmpk * s2), fmaf(xmk, s2, -xmpk * c2));
            float2 P = make_float2(Vk.x + Vm.x, Vk.y - Vm.y);   // V_k + conj(V_{M-k})
            float2 Q = make_float2(Vk.x - Vm.x, Vk.y + Vm.y);   // V_k - conj(V_{M-k})
            float2 W = csqr(csqr(make_float2(c1, s1)));          // e^{j*2pi*k/4096}
            Z[i] = make_float2(P.x - W.y * Q.x - W.x * Q.y,
                               P.y + W.x * Q.x - W.y * Q.y);
        }
        float2 X[16];
        idft16(Z, X);
        float2 w1 = tw_from_expk(expk, 2 * tid);   // W_2048^{tid}
        tw_store16(buf, X, w1, 16 * tid, 1);
    }
    __syncthreads();

    // ---- radix-16 stage 2 (S=16): in-place (regs -> sync -> write) ----
    {
        float2 a[16], X[16];
#pragma unroll
        for (int i = 0; i < 16; i++) a[i] = buf[SW(tid + 128 * i)];
        idft16(a, X);
        int p = tid >> 4, q = tid & 15;
        float2 w1 = tw_from_expk(expk, 32 * p);    // W_2048^{16p}
        __syncthreads();                            // all reads done before writes
        tw_store16(buf, X, w1, q + 256 * p, 16);
    }
    __syncthreads();

    // ---- radix-8 stage 3 (S=256, trivial twiddle) fused with output perm ----
    // Thread handles butterflies b1=tid, b2=255-tid: partner of z_{q+256i}
    // is z_{2047-(q+256i)} = z_{(255-q)+256(7-i)} -> thread-local.
    {
        const int b1 = tid, b2 = 255 - tid;
        float2 a1[8], a2[8], z1[8], z2[8];
#pragma unroll
        for (int i = 0; i < 8; i++) a1[i] = buf[SW(b1 + 256 * i)];
#pragma unroll
        for (int i = 0; i < 8; i++) a2[i] = buf[SW(b2 + 256 * i)];
        idft8(a1, z1);
        idft8(a2, z2);
        // y[4s..4s+3] = {Re z_s, Im z_{2047-s}, Im z_s, Re z_{2047-s}}
        float4* yr = (float4*)(y + (size_t)blockIdx.x * NN);
#pragma unroll
        for (int i = 0; i < 4; i++) {
            yr[b1 + 256 * i] = make_float4(z1[i].x, z2[7 - i].y, z1[i].y, z2[7 - i].x);
            yr[b2 + 256 * i] = make_float4(z2[i].x, z1[7 - i].y, z2[i].y, z1[7 - i].x);
        }
    }
}

extern "C" void kernel_launch(void* const* d_in, const int* in_sizes, int n_in,
                              void* d_out, int out_size) {
    const float*  x    = (const float*)d_in[0];
    const float2* expk = (const float2*)d_in[1];
    float*        y    = (float*)d_out;

    int rows = in_sizes[0] / NN;                 // 4096
    size_t smem_bytes = MM * sizeof(float2);     // 16 KB, single in-place buffer
    idct_kernel<<<rows, THREADS, smem_bytes>>>(x, expk, y);
}